// round 1
// baseline (speedup 1.0000x reference)
#include <cuda_runtime.h>
#include <math.h>

// ---------------- scratch (device globals; no allocation allowed) ----------
#define MROWS (4 * 8192)          // 32768 total rows
#define DIMK  512
#define NQKV  1536

__device__ float g_q[MROWS * 512];        // elu(q)+1, [row][512]
__device__ float g_k[MROWS * 512];        // elu(k)+1
__device__ float g_v[MROWS * 512];        // v
__device__ float g_kvpart[32 * 16 * 4160]; // per (bh, chunk): 64x64 kv + 64 ksum
__device__ float g_kv[32 * 4160];          // reduced: kv[d][m] then ksum[d]
__device__ float g_wbig[4 * 512 * 512];    // per-batch combined weight
__device__ float g_z[32 * 8192];           // z[(b*8+h)*8192 + n]

// ---------------- helpers --------------------------------------------------
__device__ __forceinline__ float elu1(float x) {
    return x >= 0.f ? x + 1.f : __expf(x);
}

// ============================================================================
// Kernel A: qkv = x @ w_qkv, epilogue: split into q/k/v with elu+1 on q,k
// M=32768, K=512, N=1536. 128x128x8 tile, 256 threads, 8x8 per thread.
// ============================================================================
__global__ __launch_bounds__(256, 2) void gemm_qkv(const float* __restrict__ X,
                                                   const float* __restrict__ W)
{
    __shared__ float As[8][128];
    __shared__ float Bs[8][128];
    const int tid = threadIdx.x;
    const int m0 = blockIdx.y * 128;
    const int n0 = blockIdx.x * 128;

    float acc[8][8];
#pragma unroll
    for (int i = 0; i < 8; i++)
#pragma unroll
        for (int j = 0; j < 8; j++) acc[i][j] = 0.f;

    const int arow = tid >> 1;          // 0..127
    const int acol = (tid & 1) * 4;     // 0 or 4
    const int brow = tid >> 5;          // 0..7
    const int bcol = (tid & 31) * 4;    // 0..124

    const float* Aptr = X + (size_t)(m0 + arow) * DIMK + acol;
    const float* Bptr = W + (size_t)brow * NQKV + n0 + bcol;

    const int tr = (tid >> 4) * 4;
    const int tc = (tid & 15) * 4;

    for (int k0 = 0; k0 < DIMK; k0 += 8) {
        float4 av = *(const float4*)(Aptr + k0);
        float4 bv = *(const float4*)(Bptr + (size_t)k0 * NQKV);
        As[acol + 0][arow] = av.x;
        As[acol + 1][arow] = av.y;
        As[acol + 2][arow] = av.z;
        As[acol + 3][arow] = av.w;
        *(float4*)&Bs[brow][bcol] = bv;
        __syncthreads();
#pragma unroll
        for (int k = 0; k < 8; k++) {
            float a[8], b[8];
            *(float4*)(a)     = *(float4*)&As[k][tr];
            *(float4*)(a + 4) = *(float4*)&As[k][64 + tr];
            *(float4*)(b)     = *(float4*)&Bs[k][tc];
            *(float4*)(b + 4) = *(float4*)&Bs[k][64 + tc];
#pragma unroll
            for (int i = 0; i < 8; i++)
#pragma unroll
                for (int j = 0; j < 8; j++) acc[i][j] += a[i] * b[j];
        }
        __syncthreads();
    }

    // epilogue: route to q/k/v with activation
#pragma unroll
    for (int i = 0; i < 8; i++) {
        int m = m0 + (i < 4 ? tr + i : 64 + tr + (i - 4));
#pragma unroll
        for (int jh = 0; jh < 2; jh++) {
            int c = n0 + (jh == 0 ? tc : 64 + tc);   // 4 consecutive cols from c
            float4 out;
            float v0 = acc[i][jh * 4 + 0];
            float v1 = acc[i][jh * 4 + 1];
            float v2 = acc[i][jh * 4 + 2];
            float v3 = acc[i][jh * 4 + 3];
            if (c < 1024) { v0 = elu1(v0); v1 = elu1(v1); v2 = elu1(v2); v3 = elu1(v3); }
            out.x = v0; out.y = v1; out.z = v2; out.w = v3;
            float* dst;
            int cc = c;
            if (c < 512)       { dst = g_q; }
            else if (c < 1024) { dst = g_k; cc = c - 512; }
            else               { dst = g_v; cc = c - 1024; }
            *(float4*)&dst[(size_t)m * 512 + cc] = out;
        }
    }
}

// ============================================================================
// Kernel B: per (b,h,chunk): partial kv[64][64] = sum_n k_d * v_m, ksum[64]
// grid (32 bh, 16 chunks of 512 rows), 256 threads, 4x4 accum per thread.
// ============================================================================
__global__ __launch_bounds__(256, 4) void kv_reduce()
{
    __shared__ float ks[8][64];
    __shared__ float vs[8][64];
    const int bh = blockIdx.x;
    const int b = bh >> 3, h = bh & 7;
    const int nbase = blockIdx.y * 512;
    const int tid = threadIdx.x;
    const int tx = tid & 15, ty = tid >> 4;

    float acc[4][4];
#pragma unroll
    for (int i = 0; i < 4; i++)
#pragma unroll
        for (int j = 0; j < 4; j++) acc[i][j] = 0.f;
    float ksacc[4] = {0.f, 0.f, 0.f, 0.f};

    const int lr = (tid & 127) >> 4;  // 0..7
    const int lc = tid & 15;          // 0..15
    const float* src = (tid < 128) ? g_k : g_v;
    float* sdst = (tid < 128) ? &ks[lr][lc * 4] : &vs[lr][lc * 4];

    for (int r0 = 0; r0 < 512; r0 += 8) {
        int n = nbase + r0 + lr;
        float4 val = *(const float4*)&src[((size_t)(b * 8192 + n)) * 512 + h * 64 + lc * 4];
        *(float4*)sdst = val;
        __syncthreads();
#pragma unroll
        for (int r = 0; r < 8; r++) {
            float kf[4], vf[4];
            *(float4*)kf = *(float4*)&ks[r][tx * 4];
            *(float4*)vf = *(float4*)&vs[r][ty * 4];
#pragma unroll
            for (int i = 0; i < 4; i++)
#pragma unroll
                for (int j = 0; j < 4; j++) acc[i][j] += kf[i] * vf[j];
            if (ty == 0) {
#pragma unroll
                for (int i = 0; i < 4; i++) ksacc[i] += kf[i];
            }
        }
        __syncthreads();
    }

    const size_t base = (size_t)(bh * 16 + blockIdx.y) * 4160;
#pragma unroll
    for (int i = 0; i < 4; i++)
#pragma unroll
        for (int j = 0; j < 4; j++)
            g_kvpart[base + (tx * 4 + i) * 64 + ty * 4 + j] = acc[i][j];
    if (ty == 0) {
#pragma unroll
        for (int i = 0; i < 4; i++) g_kvpart[base + 4096 + tx * 4 + i] = ksacc[i];
    }
}

// ============================================================================
// Kernel B2: reduce 16 chunk partials -> g_kv  (deterministic tree, no atomics)
// ============================================================================
__global__ void kv_combine()
{
    const int bh = blockIdx.x;
    for (int i = threadIdx.x; i < 4160; i += 256) {
        float s = 0.f;
#pragma unroll
        for (int c = 0; c < 16; c++) s += g_kvpart[(size_t)(bh * 16 + c) * 4160 + i];
        g_kv[(size_t)bh * 4160 + i] = s;
    }
}

// ============================================================================
// Kernel C: Wbig[b][h*64+d][j] = sum_m kv[b,h,d,m] * w_out[h*64+m][j]
// grid (512 rows, 4 batches), 128 threads; each thread 4 cols.
// ============================================================================
__global__ void make_wbig(const float* __restrict__ Wout)
{
    const int r = blockIdx.x;          // h*64+d
    const int b = blockIdx.y;
    const int h = r >> 6, d = r & 63;
    __shared__ float kvrow[64];
    if (threadIdx.x < 64)
        kvrow[threadIdx.x] = g_kv[(size_t)(b * 8 + h) * 4160 + d * 64 + threadIdx.x];
    __syncthreads();
    float acc[4] = {0.f, 0.f, 0.f, 0.f};
    for (int m = 0; m < 64; m++) {
        float kvv = kvrow[m];
        const float* wrow = Wout + (size_t)(h * 64 + m) * 512;
#pragma unroll
        for (int i = 0; i < 4; i++) acc[i] += kvv * wrow[threadIdx.x + i * 128];
    }
#pragma unroll
    for (int i = 0; i < 4; i++)
        g_wbig[((size_t)b * 512 + r) * 512 + threadIdx.x + i * 128] = acc[i];
}

// ============================================================================
// Kernel Z: z[(b*8+h)*8192+n] = 1 / (q_row_head . ksum + 1e-6)
// ============================================================================
__global__ void compute_z()
{
    const int idx = blockIdx.x * 512 + threadIdx.x;   // 262144 total
    const int n = idx & 8191;
    const int bh = idx >> 13;
    const int b = bh >> 3, h = bh & 7;
    const float* qrow = g_q + (size_t)(b * 8192 + n) * 512 + h * 64;
    const float* ksum = g_kv + (size_t)bh * 4160 + 4096;
    float s = 0.f;
#pragma unroll
    for (int i = 0; i < 16; i++) {
        float4 qv = *(const float4*)(qrow + i * 4);
        float4 kv = *(const float4*)(ksum + i * 4);
        s += qv.x * kv.x + qv.y * kv.y + qv.z * kv.z + qv.w * kv.w;
    }
    g_z[idx] = 1.0f / (s + 1e-6f);
}

// ============================================================================
// Kernel D: out = (q * z) @ Wbig[b] + b_out.  M=32768, N=512, K=512.
// Same tiling as gemm_qkv; A scaled by z during smem load (K-tile of 8 stays
// within one head since 8 | 64).
// ============================================================================
__global__ __launch_bounds__(256, 2) void gemm_out(const float* __restrict__ bias,
                                                   float* __restrict__ Out)
{
    __shared__ float As[8][128];
    __shared__ float Bs[8][128];
    const int tid = threadIdx.x;
    const int m0 = blockIdx.y * 128;
    const int n0 = blockIdx.x * 128;
    const int b = m0 >> 13;             // batch (blocks never straddle batches)

    float acc[8][8];
#pragma unroll
    for (int i = 0; i < 8; i++)
#pragma unroll
        for (int j = 0; j < 8; j++) acc[i][j] = 0.f;

    const int arow = tid >> 1;
    const int acol = (tid & 1) * 4;
    const int brow = tid >> 5;
    const int bcol = (tid & 31) * 4;

    const float* Aptr = g_q + (size_t)(m0 + arow) * 512 + acol;
    const float* Bbase = g_wbig + (size_t)b * 512 * 512;
    const float* Bptr = Bbase + (size_t)brow * 512 + n0 + bcol;
    const int nloc = (m0 + arow) & 8191;

    const int tr = (tid >> 4) * 4;
    const int tc = (tid & 15) * 4;

    for (int k0 = 0; k0 < 512; k0 += 8) {
        const int head = k0 >> 6;
        const float zv = g_z[(size_t)(b * 8 + head) * 8192 + nloc];
        float4 av = *(const float4*)(Aptr + k0);
        float4 bv = *(const float4*)(Bptr + (size_t)k0 * 512);
        As[acol + 0][arow] = av.x * zv;
        As[acol + 1][arow] = av.y * zv;
        As[acol + 2][arow] = av.z * zv;
        As[acol + 3][arow] = av.w * zv;
        *(float4*)&Bs[brow][bcol] = bv;
        __syncthreads();
#pragma unroll
        for (int k = 0; k < 8; k++) {
            float a[8], bb[8];
            *(float4*)(a)      = *(float4*)&As[k][tr];
            *(float4*)(a + 4)  = *(float4*)&As[k][64 + tr];
            *(float4*)(bb)     = *(float4*)&Bs[k][tc];
            *(float4*)(bb + 4) = *(float4*)&Bs[k][64 + tc];
#pragma unroll
            for (int i = 0; i < 8; i++)
#pragma unroll
                for (int j = 0; j < 8; j++) acc[i][j] += a[i] * bb[j];
        }
        __syncthreads();
    }

#pragma unroll
    for (int i = 0; i < 8; i++) {
        int m = m0 + (i < 4 ? tr + i : 64 + tr + (i - 4));
#pragma unroll
        for (int jh = 0; jh < 2; jh++) {
            int c = n0 + (jh == 0 ? tc : 64 + tc);
            float4 o;
            o.x = acc[i][jh * 4 + 0] + bias[c + 0];
            o.y = acc[i][jh * 4 + 1] + bias[c + 1];
            o.z = acc[i][jh * 4 + 2] + bias[c + 2];
            o.w = acc[i][jh * 4 + 3] + bias[c + 3];
            *(float4*)&Out[(size_t)m * 512 + c] = o;
        }
    }
}

// ============================================================================
extern "C" void kernel_launch(void* const* d_in, const int* in_sizes, int n_in,
                              void* d_out, int out_size)
{
    const float* x     = (const float*)d_in[0];   // [4,8192,512]
    const float* w_qkv = (const float*)d_in[1];   // [512,1536]
    const float* w_out = (const float*)d_in[2];   // [512,512]
    const float* b_out = (const float*)d_in[3];   // [512]
    float* out = (float*)d_out;                   // [4,8192,512]

    gemm_qkv<<<dim3(NQKV / 128, MROWS / 128), 256>>>(x, w_qkv);
    kv_reduce<<<dim3(32, 16), 256>>>();
    kv_combine<<<32, 256>>>();
    make_wbig<<<dim3(512, 4), 128>>>(w_out);
    compute_z<<<512, 512>>>();
    gemm_out<<<dim3(512 / 128, MROWS / 128), 256>>>(b_out, out);
}

// round 5
// speedup vs baseline: 1.9919x; 1.9919x over previous
#include <cuda_runtime.h>
#include <cuda_bf16.h>
#include <math.h>
#include <stdint.h>

#define MROWS (4 * 8192)          // 32768 rows total
#define DIMK  512
#define NQKV  1536

// ---------------- scratch (device globals; no allocation allowed) ----------
__device__ float g_q[MROWS * 512];          // elu(q)+1 fp32
__device__ float g_k[MROWS * 512];          // elu(k)+1 fp32
__device__ float g_v[MROWS * 512];          // v fp32
__device__ float g_kvpart[32 * 16 * 4160];  // per (bh,chunk): 64x64 kv + 64 ksum
__device__ float g_kv[32 * 4160];
__device__ float g_z[32 * 8192];
__device__ float g_wt[NQKV * 512];          // w_qkv^T fp32 [n][k]
__device__ float g_wbt[4 * 512 * 512];      // Wbig^T fp32 per batch [j][r]

// ---------------- helpers ---------------------------------------------------
__device__ __forceinline__ void mma16816(float* c, const uint32_t* a, const uint32_t* b) {
    asm volatile(
        "mma.sync.aligned.m16n8k16.row.col.f32.bf16.bf16.f32 "
        "{%0,%1,%2,%3}, {%4,%5,%6,%7}, {%8,%9}, {%0,%1,%2,%3};"
        : "+f"(c[0]), "+f"(c[1]), "+f"(c[2]), "+f"(c[3])
        : "r"(a[0]), "r"(a[1]), "r"(a[2]), "r"(a[3]), "r"(b[0]), "r"(b[1]));
}

__device__ __forceinline__ float elu1(float x) {
    return x >= 0.f ? x + 1.f : __expf(x);
}
__device__ __forceinline__ void split2(float v, __nv_bfloat16& hi, __nv_bfloat16& lo) {
    hi = __float2bfloat16_rn(v);
    lo = __float2bfloat16_rn(v - __bfloat162float(hi));
}
__device__ __forceinline__ uint32_t lds32(const __nv_bfloat16* p) {
    return *(const uint32_t*)p;
}

// ============================================================================
// W transpose: g_wt[n][k] = W[k][n]   (W: [512][1536])
// ============================================================================
__global__ void transpose_w(const float* __restrict__ W)
{
    __shared__ float t[32][33];
    const int bx = blockIdx.x * 32;   // n base
    const int by = blockIdx.y * 32;   // k base
    const int x = threadIdx.x;
    for (int yy = threadIdx.y; yy < 32; yy += 8)
        t[yy][x] = W[(size_t)(by + yy) * NQKV + bx + x];
    __syncthreads();
    for (int yy = threadIdx.y; yy < 32; yy += 8)
        g_wt[(size_t)(bx + yy) * 512 + by + x] = t[x][yy];
}

// ============================================================================
// bf16-split GEMM via mma.sync. C tile 128x128, K=512 in 16 chunks of 32.
// fp32 sources; hi/lo split done in-kernel during smem load. Single-buffered,
// static smem. 8 warps, warp tile 64x32, explicit LDS fragments (PTX tables).
// MODE 0: C = X @ W  (B = g_wt [n][k]) -> split q/k/v, elu+1 on q,k
// MODE 1: C = (q*z) @ Wbig (B = g_wbt[b] [j][r]) + bias -> Out
//         (A rows scaled by z for the head owning this k-chunk, as in R1)
// ============================================================================
#define PITCH 40                      // bf16 per smem row (80 B) -> conflict-free frags

template <int MODE>
__global__ __launch_bounds__(256) void gemm_mma(
    const float* __restrict__ Asrc, const float* __restrict__ Bsrc,
    const float* __restrict__ bias, float* __restrict__ Out)
{
    __shared__ __nv_bfloat16 sAh[128 * PITCH];
    __shared__ __nv_bfloat16 sAl[128 * PITCH];
    __shared__ __nv_bfloat16 sBh[128 * PITCH];
    __shared__ __nv_bfloat16 sBl[128 * PITCH];

    const int tid = threadIdx.x;
    const int wid = tid >> 5, lane = tid & 31;
    const int g = lane >> 2, tig = lane & 3;
    const int m0 = blockIdx.y * 128;
    const int n0 = blockIdx.x * 128;
    const int wm = (wid & 1) * 64;
    const int wn = (wid >> 1) * 32;
    const int bb = m0 >> 13;          // batch (tiles never straddle batches)

    const float* Bt = Bsrc + (MODE == 1 ? (size_t)bb * 262144 : 0);

    float acc[4][4][4];
#pragma unroll
    for (int i = 0; i < 4; i++)
#pragma unroll
        for (int j = 0; j < 4; j++)
#pragma unroll
            for (int t = 0; t < 4; t++) acc[i][j][t] = 0.f;

    for (int kc = 0; kc < 16; kc++) {
        const int k0 = kc * 32;
        __syncthreads();   // previous compute done before overwriting smem

        // ---- load + split: A and B tiles (128 rows x 32 k each) ----
#pragma unroll
        for (int i = 0; i < 4; i++) {
            int idx = tid + 256 * i;       // 0..1023 float4 slots
            int row = idx >> 3, ch = idx & 7;
            float4 va = *(const float4*)(Asrc + (size_t)(m0 + row) * 512 + k0 + ch * 4);
            if (MODE == 1) {
                float zv = g_z[(size_t)(bb * 8 + (k0 >> 6)) * 8192 + ((m0 + row) & 8191)];
                va.x *= zv; va.y *= zv; va.z *= zv; va.w *= zv;
            }
            __nv_bfloat16 h0, h1, h2, h3, l0, l1, l2, l3;
            split2(va.x, h0, l0); split2(va.y, h1, l1);
            split2(va.z, h2, l2); split2(va.w, h3, l3);
            int so = row * PITCH + ch * 4;
            *(__nv_bfloat162*)&sAh[so]     = __nv_bfloat162(h0, h1);
            *(__nv_bfloat162*)&sAh[so + 2] = __nv_bfloat162(h2, h3);
            *(__nv_bfloat162*)&sAl[so]     = __nv_bfloat162(l0, l1);
            *(__nv_bfloat162*)&sAl[so + 2] = __nv_bfloat162(l2, l3);

            float4 vb = *(const float4*)(Bt + (size_t)(n0 + row) * 512 + k0 + ch * 4);
            split2(vb.x, h0, l0); split2(vb.y, h1, l1);
            split2(vb.z, h2, l2); split2(vb.w, h3, l3);
            *(__nv_bfloat162*)&sBh[so]     = __nv_bfloat162(h0, h1);
            *(__nv_bfloat162*)&sBh[so + 2] = __nv_bfloat162(h2, h3);
            *(__nv_bfloat162*)&sBl[so]     = __nv_bfloat162(l0, l1);
            *(__nv_bfloat162*)&sBl[so + 2] = __nv_bfloat162(l2, l3);
        }
        __syncthreads();

        // ---- compute: 2 k-halves of 16, explicit fragment loads ----
#pragma unroll
        for (int ks = 0; ks < 2; ks++) {
            const int ko = ks * 16 + tig * 2;
            uint32_t ah[4][4], al[4][4];
#pragma unroll
            for (int mt = 0; mt < 4; mt++) {
                const int r = wm + mt * 16 + g;
                ah[mt][0] = lds32(sAh + r * PITCH + ko);
                ah[mt][1] = lds32(sAh + (r + 8) * PITCH + ko);
                ah[mt][2] = lds32(sAh + r * PITCH + ko + 8);
                ah[mt][3] = lds32(sAh + (r + 8) * PITCH + ko + 8);
                al[mt][0] = lds32(sAl + r * PITCH + ko);
                al[mt][1] = lds32(sAl + (r + 8) * PITCH + ko);
                al[mt][2] = lds32(sAl + r * PITCH + ko + 8);
                al[mt][3] = lds32(sAl + (r + 8) * PITCH + ko + 8);
            }
            uint32_t bh[4][2], bl[4][2];
#pragma unroll
            for (int nt = 0; nt < 4; nt++) {
                const int rn = wn + nt * 8 + g;
                bh[nt][0] = lds32(sBh + rn * PITCH + ko);
                bh[nt][1] = lds32(sBh + rn * PITCH + ko + 8);
                bl[nt][0] = lds32(sBl + rn * PITCH + ko);
                bl[nt][1] = lds32(sBl + rn * PITCH + ko + 8);
            }
#pragma unroll
            for (int mt = 0; mt < 4; mt++)
#pragma unroll
                for (int nt = 0; nt < 4; nt++) {
                    mma16816(acc[mt][nt], ah[mt], bh[nt]);
                    mma16816(acc[mt][nt], ah[mt], bl[nt]);
                    mma16816(acc[mt][nt], al[mt], bh[nt]);
                }
        }
    }

    // -------- epilogue (C table: c0,c1=(g, t*2); c2,c3=(g+8, t*2)) --------
    if (MODE == 0) {
        float* dst = (n0 < 512) ? g_q : (n0 < 1024 ? g_k : g_v);
        const bool act = (n0 < 1024);
        const int cb = (n0 & 511) + wn;
#pragma unroll
        for (int mt = 0; mt < 4; mt++) {
            int r0 = m0 + wm + mt * 16 + g;
#pragma unroll
            for (int nt = 0; nt < 4; nt++) {
                int c = cb + nt * 8 + tig * 2;
                float v0 = acc[mt][nt][0], v1 = acc[mt][nt][1];
                float v2 = acc[mt][nt][2], v3 = acc[mt][nt][3];
                if (act) { v0 = elu1(v0); v1 = elu1(v1); v2 = elu1(v2); v3 = elu1(v3); }
                *(float2*)&dst[(size_t)r0 * 512 + c]       = make_float2(v0, v1);
                *(float2*)&dst[(size_t)(r0 + 8) * 512 + c] = make_float2(v2, v3);
            }
        }
    } else {
        const int cb = n0 + wn;
#pragma unroll
        for (int mt = 0; mt < 4; mt++) {
            int r0 = m0 + wm + mt * 16 + g;
#pragma unroll
            for (int nt = 0; nt < 4; nt++) {
                int c = cb + nt * 8 + tig * 2;
                float b0 = bias[c], b1 = bias[c + 1];
                *(float2*)&Out[(size_t)r0 * 512 + c] =
                    make_float2(acc[mt][nt][0] + b0, acc[mt][nt][1] + b1);
                *(float2*)&Out[(size_t)(r0 + 8) * 512 + c] =
                    make_float2(acc[mt][nt][2] + b0, acc[mt][nt][3] + b1);
            }
        }
    }
}

// ============================================================================
// kv partial reduce + combine (fp32 SIMT, verbatim from R1-passing kernel)
// ============================================================================
__global__ __launch_bounds__(256, 4) void kv_reduce()
{
    __shared__ float ks[8][64];
    __shared__ float vs[8][64];
    const int bh = blockIdx.x;
    const int b = bh >> 3, h = bh & 7;
    const int nbase = blockIdx.y * 512;
    const int tid = threadIdx.x;
    const int tx = tid & 15, ty = tid >> 4;

    float acc[4][4];
#pragma unroll
    for (int i = 0; i < 4; i++)
#pragma unroll
        for (int j = 0; j < 4; j++) acc[i][j] = 0.f;
    float ksacc[4] = {0.f, 0.f, 0.f, 0.f};

    const int lr = (tid & 127) >> 4;
    const int lc = tid & 15;
    const float* src = (tid < 128) ? g_k : g_v;
    float* sdst = (tid < 128) ? &ks[lr][lc * 4] : &vs[lr][lc * 4];

    for (int r0 = 0; r0 < 512; r0 += 8) {
        int n = nbase + r0 + lr;
        float4 val = *(const float4*)&src[((size_t)(b * 8192 + n)) * 512 + h * 64 + lc * 4];
        *(float4*)sdst = val;
        __syncthreads();
#pragma unroll
        for (int r = 0; r < 8; r++) {
            float kf[4], vf[4];
            *(float4*)kf = *(float4*)&ks[r][tx * 4];
            *(float4*)vf = *(float4*)&vs[r][ty * 4];
#pragma unroll
            for (int i = 0; i < 4; i++)
#pragma unroll
                for (int j = 0; j < 4; j++) acc[i][j] += kf[i] * vf[j];
            if (ty == 0) {
#pragma unroll
                for (int i = 0; i < 4; i++) ksacc[i] += kf[i];
            }
        }
        __syncthreads();
    }

    const size_t base = (size_t)(bh * 16 + blockIdx.y) * 4160;
#pragma unroll
    for (int i = 0; i < 4; i++)
#pragma unroll
        for (int j = 0; j < 4; j++)
            g_kvpart[base + (tx * 4 + i) * 64 + ty * 4 + j] = acc[i][j];
    if (ty == 0) {
#pragma unroll
        for (int i = 0; i < 4; i++) g_kvpart[base + 4096 + tx * 4 + i] = ksacc[i];
    }
}

__global__ void kv_combine()
{
    const int bh = blockIdx.x;
    for (int i = threadIdx.x; i < 4160; i += 256) {
        float s = 0.f;
#pragma unroll
        for (int c = 0; c < 16; c++) s += g_kvpart[(size_t)(bh * 16 + c) * 4160 + i];
        g_kv[(size_t)bh * 4160 + i] = s;
    }
}

// ============================================================================
// Wbig^T fp32: g_wbt[b][j][r] = sum_m kv[b,h,d,m] * w_out[h*64+m][j], r=h*64+d
// (R1-verified compute; only the store index is transposed)
// ============================================================================
__global__ void make_wbig(const float* __restrict__ Wout)
{
    const int r = blockIdx.x;          // h*64+d
    const int b = blockIdx.y;
    const int h = r >> 6, d = r & 63;
    __shared__ float kvrow[64];
    if (threadIdx.x < 64)
        kvrow[threadIdx.x] = g_kv[(size_t)(b * 8 + h) * 4160 + d * 64 + threadIdx.x];
    __syncthreads();
    float acc[4] = {0.f, 0.f, 0.f, 0.f};
    for (int m = 0; m < 64; m++) {
        float kvv = kvrow[m];
        const float* wrow = Wout + (size_t)(h * 64 + m) * 512;
#pragma unroll
        for (int i = 0; i < 4; i++) acc[i] += kvv * wrow[threadIdx.x + i * 128];
    }
#pragma unroll
    for (int i = 0; i < 4; i++) {
        int j = threadIdx.x + i * 128;
        g_wbt[(size_t)b * 262144 + (size_t)j * 512 + r] = acc[i];
    }
}

// ============================================================================
// z = 1 / (q . ksum + 1e-6)    (verbatim from R1)
// ============================================================================
__global__ void compute_z()
{
    const int idx = blockIdx.x * 512 + threadIdx.x;
    const int n = idx & 8191;
    const int bh = idx >> 13;
    const int b = bh >> 3, h = bh & 7;
    const float* qrow = g_q + (size_t)(b * 8192 + n) * 512 + h * 64;
    const float* ksum = g_kv + (size_t)bh * 4160 + 4096;
    float s = 0.f;
#pragma unroll
    for (int i = 0; i < 16; i++) {
        float4 qv = *(const float4*)(qrow + i * 4);
        float4 kv = *(const float4*)(ksum + i * 4);
        s += qv.x * kv.x + qv.y * kv.y + qv.z * kv.z + qv.w * kv.w;
    }
    g_z[idx] = 1.0f / (s + 1e-6f);
}

// ============================================================================
extern "C" void kernel_launch(void* const* d_in, const int* in_sizes, int n_in,
                              void* d_out, int out_size)
{
    const float* x     = (const float*)d_in[0];   // [4,8192,512]
    const float* w_qkv = (const float*)d_in[1];   // [512,1536]
    const float* w_out = (const float*)d_in[2];   // [512,512]
    const float* b_out = (const float*)d_in[3];   // [512]
    float* out = (float*)d_out;                   // [4,8192,512]

    // resolve device-global addresses for kernel arguments
    float* wt_p;   cudaGetSymbolAddress((void**)&wt_p,  g_wt);
    float* wbt_p;  cudaGetSymbolAddress((void**)&wbt_p, g_wbt);
    float* q_p;    cudaGetSymbolAddress((void**)&q_p,   g_q);

    transpose_w<<<dim3(48, 16), dim3(32, 8)>>>(w_qkv);
    gemm_mma<0><<<dim3(12, 256), 256>>>(x, wt_p, nullptr, nullptr);
    kv_reduce<<<dim3(32, 16), 256>>>();
    kv_combine<<<32, 256>>>();
    make_wbig<<<dim3(512, 4), 128>>>(w_out);
    compute_z<<<512, 512>>>();
    gemm_mma<1><<<dim3(4, 256), 256>>>(q_p, wbt_p, b_out, out);
}